// round 2
// baseline (speedup 1.0000x reference)
#include <cuda_runtime.h>
#include <cstdint>
#include <cmath>

// Problem constants
#define BB 16
#define HH 512
#define LL 2048
#define NN 32
#define TT 64          // chunk length
#define CCH 32         // number of chunks = LL/TT
#define PI_F 3.14159265358979323846f

// ---------------- scratch (static device arrays; no allocation) ----------------
__device__ float  g_yg[8192 * 2048];                      // gelu(conv) output (B*H) x L
__device__ float  g_y2[8192 * 1024];                      // tanh(GEMM1) output
__device__ __align__(16) float2 g_Ec[512 * 64 * 32];      // Ecross[h][i][n] = 2*Chat*w^(i+1)
__device__ float  g_ktap[512 * 64];                       // ktap[h][d] = 2 Re sum_n Chat w^d
__device__ float2 g_w [512 * 32];                         // w  = exp(dt*A)
__device__ float2 g_wT[512 * 32];                         // w^T

// =====================================================================
// Kernel 1: per-h prep (w, w^T, Chat, Ecross table, ktap taps)
// =====================================================================
__global__ void __launch_bounds__(256) prep_kernel(const float* __restrict__ log_dt,
                                                   const float* __restrict__ C_re,
                                                   const float* __restrict__ C_im) {
    __shared__ float2 chat_sh[32];
    const int h   = blockIdx.x;
    const int tid = threadIdx.x;
    const float dt = expf(log_dt[h]);

    if (tid < 32) {
        const int n = tid;
        const float Are = -0.5f, Aim = PI_F * (float)n;
        float m1 = expf(-0.5f * dt);
        float s1, c1; sincosf(Aim * dt, &s1, &c1);
        const float er = m1 * c1, ei = m1 * s1;            // w = exp(dt*A)
        g_w[h * 32 + n] = make_float2(er, ei);
        float mT = expf(-0.5f * dt * (float)TT);
        float sT, cT; sincosf(Aim * dt * (float)TT, &sT, &cT);
        g_wT[h * 32 + n] = make_float2(mT * cT, mT * sT);  // w^T
        // Chat = (C_re + i C_im) * (w - 1) / A
        const float nr = er - 1.f, ni = ei;
        const float inv = 1.f / (Are * Are + Aim * Aim);
        const float fr = (nr * Are + ni * Aim) * inv;
        const float fi = (ni * Are - nr * Aim) * inv;
        const float cr = C_re[h * 32 + n], ci = C_im[h * 32 + n];
        chat_sh[n] = make_float2(cr * fr - ci * fi, cr * fi + ci * fr);
    }
    __syncthreads();

    // Ecross[h][i][n] = 2 * Chat_n * w_n^(i+1),  i in [0,64)
#pragma unroll
    for (int rep = 0; rep < 8; ++rep) {
        const int idx = tid + rep * 256;
        const int i = idx >> 5, n = idx & 31;
        const float l = (float)(i + 1);
        const float dtl = expf(log_dt[h]) * l;
        const float mm = expf(-0.5f * dtl);
        float s, c; sincosf(PI_F * (float)n * dtl, &s, &c);
        const float wr = mm * c, wi = mm * s;
        const float2 ch = chat_sh[n];
        g_Ec[(h * 64 + i) * 32 + n] =
            make_float2(2.f * (ch.x * wr - ch.y * wi), 2.f * (ch.x * wi + ch.y * wr));
    }

    // ktap[h][d] = 2 Re sum_n Chat_n w_n^d,  d in [0,64)
    const int warp = tid >> 5, n = tid & 31;
    const float2 ch = chat_sh[n];
    for (int d = warp; d < 64; d += 8) {
        const float dtl = dt * (float)d;
        const float mm = expf(-0.5f * dtl);
        float s, c; sincosf(PI_F * (float)n * dtl, &s, &c);
        float v = 2.f * (ch.x * (mm * c) - ch.y * (mm * s));
#pragma unroll
        for (int o = 16; o > 0; o >>= 1) v += __shfl_xor_sync(0xffffffffu, v, o);
        if (n == 0) g_ktap[h * 64 + d] = v;
    }
}

// =====================================================================
// Kernel 2: chunked-scan S4D conv + D*u + exact gelu -> g_yg
// One block per (b,h). 256 threads.
// =====================================================================
__global__ void __launch_bounds__(256) conv_kernel(const float* __restrict__ u,
                                                   const float* __restrict__ D) {
    __shared__ float  u_s[CCH * 65];                   // 65-stride padding
    __shared__ __align__(16) float2 Ec_s[TT * 32];     // [i][n]
    __shared__ float2 S_s[CCH * 33 + 1];               // [c][n] padded
    __shared__ float  ktap_s[TT];
    __shared__ float2 wsh[32], wTsh[32];

    const int tid = threadIdx.x;
    const int bh  = blockIdx.x;
    const int h   = bh >> 4;       // h-major: Ecross/ktap stay hot in L2
    const int b   = bh & 15;
    const int m   = b * HH + h;

    // ---- load u row (coalesced float4) into padded smem layout
    const float4* ug = (const float4*)(u + (size_t)m * LL);
#pragma unroll
    for (int r = 0; r < 2; ++r) {
        const int v = tid + r * 256;            // float4 index, 512 total
        const float4 x = ug[v];
        const int l = v * 4;
        float* p = &u_s[(l >> 6) * 65 + (l & 63)];
        p[0] = x.x; p[1] = x.y; p[2] = x.z; p[3] = x.w;
    }
    // ---- load Ecross (16KB) / ktap / w / wT
    {
        const float4* eg = (const float4*)(g_Ec + (size_t)h * TT * 32);
        float4* es = (float4*)Ec_s;
#pragma unroll
        for (int r = 0; r < 4; ++r) es[tid + r * 256] = eg[tid + r * 256];
    }
    if (tid < TT) ktap_s[tid] = g_ktap[h * TT + tid];
    if (tid < 32) { wsh[tid] = g_w[h * 32 + tid]; wTsh[tid] = g_wT[h * 32 + tid]; }
    __syncthreads();

    // ---- phase 1: chunk summaries r[c][n] = sum_j w^(T-1-j) u[cT+j]  (Horner)
#pragma unroll
    for (int r = 0; r < 4; ++r) {
        const int task = tid + r * 256;
        const int n = task & 31, c = task >> 5;
        const float2 w = wsh[n];
        float rr = 0.f, ri = 0.f;
        const float* up = &u_s[c * 65];
#pragma unroll 8
        for (int j = 0; j < TT; ++j) {
            const float uj = up[j];
            const float nrr = fmaf(rr, w.x, fmaf(-ri, w.y, uj));
            const float nri = fmaf(rr, w.y, ri * w.x);
            rr = nrr; ri = nri;
        }
        S_s[c * 33 + n] = make_float2(rr, ri);
    }
    __syncthreads();

    // ---- phase 2: carry scan over chunks (one warp, lane = mode)
    if (tid < 32) {
        const int n = tid;
        const float2 wT = wTsh[n];
        float sr = 0.f, si = 0.f;
        for (int c = 0; c < CCH; ++c) {
            const float2 rv = S_s[c * 33 + n];
            S_s[c * 33 + n] = make_float2(sr, si);     // state entering chunk c
            const float nsr = fmaf(sr, wT.x, fmaf(-si, wT.y, rv.x));
            const float nsi = fmaf(sr, wT.y, fmaf(si, wT.x, rv.y));
            sr = nsr; si = nsi;
        }
    }
    __syncthreads();

    // ---- phase 3: outputs. lane = chunk, sub-warp picks 8 consecutive offsets
    const int c   = tid & 31;
    const int sub = tid >> 5;
    const int i0  = sub * 8;
    const float* urow = &u_s[c * 65];

    float acc[8];
#pragma unroll
    for (int t = 0; t < 8; ++t) acc[t] = 0.f;

    // intra-chunk real conv with ktap (sliding register window over u)
    float uw[8];
#pragma unroll
    for (int t = 0; t < 8; ++t) uw[t] = urow[i0 + t];
    const int dmax = i0 + 8;
#pragma unroll 8
    for (int d = 0; d < dmax; ++d) {
        const float kd = ktap_s[d];
#pragma unroll
        for (int t = 0; t < 8; ++t) acc[t] = fmaf(kd, uw[t], acc[t]);
#pragma unroll
        for (int t = 7; t > 0; --t) uw[t] = uw[t - 1];
        const int src = i0 - d - 1;
        uw[0] = (src >= 0) ? urow[src] : 0.f;
    }

    // cross term: 2 Re sum_n Ecross[i][n] * S[c][n]
#pragma unroll 4
    for (int n = 0; n < 32; ++n) {
        const float2 s = S_s[c * 33 + n];
#pragma unroll
        for (int t = 0; t < 8; ++t) {
            const float2 e = Ec_s[(i0 + t) * 32 + n];
            acc[t] = fmaf(e.x, s.x, fmaf(-e.y, s.y, acc[t]));
        }
    }

    // + D*u, exact gelu
    const float Dv = D[h];
#pragma unroll
    for (int t = 0; t < 8; ++t) {
        const float y = fmaf(Dv, urow[i0 + t], acc[t]);
        acc[t] = 0.5f * y * (1.f + erff(y * 0.70710678118654752f));
    }
    __syncthreads();
    // stage to smem, then coalesced global store
#pragma unroll
    for (int t = 0; t < 8; ++t) u_s[c * 65 + i0 + t] = acc[t];
    __syncthreads();
    float* yo = g_yg + (size_t)m * LL;
#pragma unroll
    for (int r = 0; r < 8; ++r) {
        const int l = tid + r * 256;
        yo[l] = u_s[(l >> 6) * 65 + (l & 63)];
    }
}

// =====================================================================
// SIMT fp32 GEMM: C = act(A[MxK] @ B[KxN] + bias)
// 128x128 block tile, K-slab 16, 256 threads, 8x8 register blocking.
// =====================================================================
template<int KDIM, bool DO_TANH>
__global__ void __launch_bounds__(256, 2) gemm_kernel(const float* __restrict__ A,
                                                      const float* __restrict__ B,
                                                      const float* __restrict__ bias,
                                                      float* __restrict__ C,
                                                      int N) {
    __shared__ float As[16][132];   // transposed A slab: As[k][m], padded
    __shared__ float Bs[16][128];   // Bs[k][n]

    const int tid = threadIdx.x;
    const int m0  = blockIdx.y * 128;
    const int n0  = blockIdx.x * 128;
    const int ty  = tid >> 4, tx = tid & 15;
    const int tm  = ty * 8,  tn = tx * 8;

    float acc[8][8];
#pragma unroll
    for (int i = 0; i < 8; ++i)
#pragma unroll
        for (int j = 0; j < 8; ++j) acc[i][j] = 0.f;

    const float* Ag = A + (size_t)m0 * KDIM;
    const float* Bg = B + n0;

    // per-thread load indices (512 float4 per tile, 2 per thread)
    const int av0 = tid,        av1 = tid + 256;
    const int ar0 = av0 >> 2,   ac0 = (av0 & 3) * 4;
    const int ar1 = av1 >> 2,   ac1 = (av1 & 3) * 4;
    const int bk0 = av0 >> 5,   bn0 = (av0 & 31) * 4;
    const int bk1 = av1 >> 5,   bn1 = (av1 & 31) * 4;

    for (int kt = 0; kt < KDIM; kt += 16) {
        const float4 a0 = *(const float4*)(Ag + (size_t)ar0 * KDIM + kt + ac0);
        const float4 a1 = *(const float4*)(Ag + (size_t)ar1 * KDIM + kt + ac1);
        const float4 b0 = *(const float4*)(Bg + (size_t)(kt + bk0) * N + bn0);
        const float4 b1 = *(const float4*)(Bg + (size_t)(kt + bk1) * N + bn1);
        __syncthreads();               // previous slab fully consumed
        As[ac0 + 0][ar0] = a0.x; As[ac0 + 1][ar0] = a0.y;
        As[ac0 + 2][ar0] = a0.z; As[ac0 + 3][ar0] = a0.w;
        As[ac1 + 0][ar1] = a1.x; As[ac1 + 1][ar1] = a1.y;
        As[ac1 + 2][ar1] = a1.z; As[ac1 + 3][ar1] = a1.w;
        *(float4*)&Bs[bk0][bn0] = b0;
        *(float4*)&Bs[bk1][bn1] = b1;
        __syncthreads();
#pragma unroll
        for (int k = 0; k < 16; ++k) {
            float a[8], b[8];
            *(float4*)(a)     = *(const float4*)&As[k][tm];
            *(float4*)(a + 4) = *(const float4*)&As[k][tm + 4];
            *(float4*)(b)     = *(const float4*)&Bs[k][tn];
            *(float4*)(b + 4) = *(const float4*)&Bs[k][tn + 4];
#pragma unroll
            for (int i = 0; i < 8; ++i)
#pragma unroll
                for (int j = 0; j < 8; ++j)
                    acc[i][j] = fmaf(a[i], b[j], acc[i][j]);
        }
    }

    // epilogue: bias + activation
    float bv[8];
#pragma unroll
    for (int j = 0; j < 8; ++j) bv[j] = bias[n0 + tn + j];
#pragma unroll
    for (int i = 0; i < 8; ++i) {
        float* crow = C + (size_t)(m0 + tm + i) * N + n0 + tn;
        float4 o0, o1;
        float v[8];
#pragma unroll
        for (int j = 0; j < 8; ++j) {
            float x = acc[i][j] + bv[j];
            v[j] = DO_TANH ? tanhf(x) : x;
        }
        o0 = make_float4(v[0], v[1], v[2], v[3]);
        o1 = make_float4(v[4], v[5], v[6], v[7]);
        *(float4*)(crow)     = o0;
        *(float4*)(crow + 4) = o1;
    }
}

// =====================================================================
extern "C" void kernel_launch(void* const* d_in, const int* in_sizes, int n_in,
                              void* d_out, int out_size) {
    (void)in_sizes; (void)n_in; (void)out_size;
    const float* u      = (const float*)d_in[0];
    const float* D      = (const float*)d_in[1];
    const float* log_dt = (const float*)d_in[2];
    const float* C_re   = (const float*)d_in[3];
    const float* C_im   = (const float*)d_in[4];
    const float* W1     = (const float*)d_in[5];
    const float* b1     = (const float*)d_in[6];
    const float* W2     = (const float*)d_in[7];
    const float* b2     = (const float*)d_in[8];
    float* out = (float*)d_out;

    float *yg_p, *y2_p;
    cudaGetSymbolAddress((void**)&yg_p, g_yg);
    cudaGetSymbolAddress((void**)&y2_p, g_y2);

    prep_kernel<<<HH, 256>>>(log_dt, C_re, C_im);
    conv_kernel<<<BB * HH, 256>>>(u, D);
    // GEMM1: (8192 x 2048) @ (2048 x 1024) + b1 -> tanh -> g_y2
    gemm_kernel<2048, true><<<dim3(1024 / 128, 8192 / 128), 256>>>(yg_p, W1, b1, y2_p, 1024);
    // GEMM2: (8192 x 1024) @ (1024 x 512) + b2 -> out
    gemm_kernel<1024, false><<<dim3(512 / 128, 8192 / 128), 256>>>(y2_p, W2, b2, out, 512);
}

// round 5
// speedup vs baseline: 2.1148x; 2.1148x over previous
#include <cuda_runtime.h>
#include <cstdint>
#include <cmath>

// Problem constants
#define BB 16
#define HH 512
#define LL 2048
#define NN 32
#define TT 64          // chunk length
#define CCH 32         // number of chunks = LL/TT
#define PI_F 3.14159265358979323846f

// ---------------- scratch (static device arrays; no allocation) ----------------
__device__ float  g_yg[8192 * 2048];                      // gelu(conv) output (B*H) x L (tf32-rounded)
__device__ float  g_y2[8192 * 1024];                      // tanh(GEMM1) output (tf32-rounded)
__device__ float  g_W1T[1024 * 2048];                     // W1^T, tf32-rounded
__device__ float  g_W2T[512 * 1024];                      // W2^T, tf32-rounded
__device__ __align__(16) float2 g_Ec[512 * 64 * 32];      // Ecross[h][i][n] = 2*Chat*w^(i+1)
__device__ float  g_ktap[512 * 64];                       // ktap[h][d] = 2 Re sum_n Chat w^d
__device__ float2 g_w [512 * 32];                         // w  = exp(dt*A)
__device__ float2 g_wT[512 * 32];                         // w^T

__device__ __forceinline__ float to_tf32(float x) {
    uint32_t u; asm("cvt.rna.tf32.f32 %0, %1;" : "=r"(u) : "f"(x));
    return __uint_as_float(u);
}

// =====================================================================
// Kernel 1: per-h prep (w, w^T, Chat, Ecross table, ktap taps)
// =====================================================================
__global__ void __launch_bounds__(256) prep_kernel(const float* __restrict__ log_dt,
                                                   const float* __restrict__ C_re,
                                                   const float* __restrict__ C_im) {
    __shared__ float2 chat_sh[32];
    const int h   = blockIdx.x;
    const int tid = threadIdx.x;
    const float dt = expf(log_dt[h]);

    if (tid < 32) {
        const int n = tid;
        const float Are = -0.5f, Aim = PI_F * (float)n;
        float m1 = expf(-0.5f * dt);
        float s1, c1; sincosf(Aim * dt, &s1, &c1);
        const float er = m1 * c1, ei = m1 * s1;            // w = exp(dt*A)
        g_w[h * 32 + n] = make_float2(er, ei);
        float mT = expf(-0.5f * dt * (float)TT);
        float sT, cT; sincosf(Aim * dt * (float)TT, &sT, &cT);
        g_wT[h * 32 + n] = make_float2(mT * cT, mT * sT);  // w^T
        // Chat = (C_re + i C_im) * (w - 1) / A
        const float nr = er - 1.f, ni = ei;
        const float inv = 1.f / (Are * Are + Aim * Aim);
        const float fr = (nr * Are + ni * Aim) * inv;
        const float fi = (ni * Are - nr * Aim) * inv;
        const float cr = C_re[h * 32 + n], ci = C_im[h * 32 + n];
        chat_sh[n] = make_float2(cr * fr - ci * fi, cr * fi + ci * fr);
    }
    __syncthreads();

    // Ecross[h][i][n] = 2 * Chat_n * w_n^(i+1),  i in [0,64)
#pragma unroll
    for (int rep = 0; rep < 8; ++rep) {
        const int idx = tid + rep * 256;
        const int i = idx >> 5, n = idx & 31;
        const float l = (float)(i + 1);
        const float dtl = dt * l;
        const float mm = expf(-0.5f * dtl);
        float s, c; sincosf(PI_F * (float)n * dtl, &s, &c);
        const float wr = mm * c, wi = mm * s;
        const float2 ch = chat_sh[n];
        g_Ec[(h * 64 + i) * 32 + n] =
            make_float2(2.f * (ch.x * wr - ch.y * wi), 2.f * (ch.x * wi + ch.y * wr));
    }

    // ktap[h][d] = 2 Re sum_n Chat_n w_n^d,  d in [0,64)
    const int warp = tid >> 5, n = tid & 31;
    const float2 ch = chat_sh[n];
    for (int d = warp; d < 64; d += 8) {
        const float dtl = dt * (float)d;
        const float mm = expf(-0.5f * dtl);
        float s, c; sincosf(PI_F * (float)n * dtl, &s, &c);
        float v = 2.f * (ch.x * (mm * c) - ch.y * (mm * s));
#pragma unroll
        for (int o = 16; o > 0; o >>= 1) v += __shfl_xor_sync(0xffffffffu, v, o);
        if (n == 0) g_ktap[h * 64 + d] = v;
    }
}

// =====================================================================
// Kernel 2: chunked-scan S4D conv + D*u + exact gelu -> g_yg (tf32-rounded)
// =====================================================================
__global__ void __launch_bounds__(256) conv_kernel(const float* __restrict__ u,
                                                   const float* __restrict__ D) {
    __shared__ float  u_s[CCH * 65];
    __shared__ __align__(16) float2 Ec_s[TT * 32];
    __shared__ float2 S_s[CCH * 33 + 1];
    __shared__ float  ktap_s[TT];
    __shared__ float2 wsh[32], wTsh[32];

    const int tid = threadIdx.x;
    const int bh  = blockIdx.x;
    const int h   = bh >> 4;
    const int b   = bh & 15;
    const int m   = b * HH + h;

    const float4* ug = (const float4*)(u + (size_t)m * LL);
#pragma unroll
    for (int r = 0; r < 2; ++r) {
        const int v = tid + r * 256;
        const float4 x = ug[v];
        const int l = v * 4;
        float* p = &u_s[(l >> 6) * 65 + (l & 63)];
        p[0] = x.x; p[1] = x.y; p[2] = x.z; p[3] = x.w;
    }
    {
        const float4* eg = (const float4*)(g_Ec + (size_t)h * TT * 32);
        float4* es = (float4*)Ec_s;
#pragma unroll
        for (int r = 0; r < 4; ++r) es[tid + r * 256] = eg[tid + r * 256];
    }
    if (tid < TT) ktap_s[tid] = g_ktap[h * TT + tid];
    if (tid < 32) { wsh[tid] = g_w[h * 32 + tid]; wTsh[tid] = g_wT[h * 32 + tid]; }
    __syncthreads();

    // phase 1: chunk summaries (Horner)
#pragma unroll
    for (int r = 0; r < 4; ++r) {
        const int task = tid + r * 256;
        const int n = task & 31, c = task >> 5;
        const float2 w = wsh[n];
        float rr = 0.f, ri = 0.f;
        const float* up = &u_s[c * 65];
#pragma unroll 8
        for (int j = 0; j < TT; ++j) {
            const float uj = up[j];
            const float nrr = fmaf(rr, w.x, fmaf(-ri, w.y, uj));
            const float nri = fmaf(rr, w.y, ri * w.x);
            rr = nrr; ri = nri;
        }
        S_s[c * 33 + n] = make_float2(rr, ri);
    }
    __syncthreads();

    // phase 2: carry scan (one warp)
    if (tid < 32) {
        const int n = tid;
        const float2 wT = wTsh[n];
        float sr = 0.f, si = 0.f;
        for (int c = 0; c < CCH; ++c) {
            const float2 rv = S_s[c * 33 + n];
            S_s[c * 33 + n] = make_float2(sr, si);
            const float nsr = fmaf(sr, wT.x, fmaf(-si, wT.y, rv.x));
            const float nsi = fmaf(sr, wT.y, fmaf(si, wT.x, rv.y));
            sr = nsr; si = nsi;
        }
    }
    __syncthreads();

    // phase 3: outputs
    const int c   = tid & 31;
    const int sub = tid >> 5;
    const int i0  = sub * 8;
    const float* urow = &u_s[c * 65];

    float acc[8];
#pragma unroll
    for (int t = 0; t < 8; ++t) acc[t] = 0.f;

    float uw[8];
#pragma unroll
    for (int t = 0; t < 8; ++t) uw[t] = urow[i0 + t];
    const int dmax = i0 + 8;
#pragma unroll 8
    for (int d = 0; d < dmax; ++d) {
        const float kd = ktap_s[d];
#pragma unroll
        for (int t = 0; t < 8; ++t) acc[t] = fmaf(kd, uw[t], acc[t]);
#pragma unroll
        for (int t = 7; t > 0; --t) uw[t] = uw[t - 1];
        const int src = i0 - d - 1;
        uw[0] = (src >= 0) ? urow[src] : 0.f;
    }

#pragma unroll 4
    for (int n = 0; n < 32; ++n) {
        const float2 s = S_s[c * 33 + n];
#pragma unroll
        for (int t = 0; t < 8; ++t) {
            const float2 e = Ec_s[(i0 + t) * 32 + n];
            acc[t] = fmaf(e.x, s.x, fmaf(-e.y, s.y, acc[t]));
        }
    }

    const float Dv = D[h];
#pragma unroll
    for (int t = 0; t < 8; ++t) {
        const float y = fmaf(Dv, urow[i0 + t], acc[t]);
        acc[t] = 0.5f * y * (1.f + erff(y * 0.70710678118654752f));
    }
    __syncthreads();
#pragma unroll
    for (int t = 0; t < 8; ++t) u_s[c * 65 + i0 + t] = acc[t];
    __syncthreads();
    float* yo = g_yg + (size_t)m * LL;
#pragma unroll
    for (int r = 0; r < 8; ++r) {
        const int l = tid + r * 256;
        yo[l] = to_tf32(u_s[(l >> 6) * 65 + (l & 63)]);
    }
}

// =====================================================================
// Weight transpose + tf32 rounding: W[K][N] -> WT[N][K]
// =====================================================================
__global__ void __launch_bounds__(256) transpose_tf32(const float* __restrict__ W,
                                                      float* __restrict__ WT,
                                                      int K, int N) {
    __shared__ float t[32][33];
    const int k0 = blockIdx.y * 32, n0 = blockIdx.x * 32;
    const int x = threadIdx.x & 31, y = threadIdx.x >> 5;   // 32x8
#pragma unroll
    for (int i = 0; i < 32; i += 8)
        t[y + i][x] = W[(size_t)(k0 + y + i) * N + n0 + x];
    __syncthreads();
#pragma unroll
    for (int i = 0; i < 32; i += 8)
        WT[(size_t)(n0 + y + i) * K + k0 + x] = to_tf32(t[x][y + i]);
}

// =====================================================================
// tf32 tensor-core GEMM: C = act(A[MxK] @ BT[NxK]^T + bias)
// 128x128 tile, BK=16, 256 threads (8 warps, warp tile 64x32),
// STATIC double-buffered smem (<=48KB, no attribute opt-in needed),
// cp.async + mma.sync.m16n8k8 tf32.
// =====================================================================
#define LDP 20                    // padded row stride (16 + 4)
#define SLOTF (128 * LDP)         // floats per buffer slot (2560)
#define SLOTB (SLOTF * 4)         // bytes per slot (10240)

__device__ __forceinline__ void cp16(uint32_t d, const void* s) {
    asm volatile("cp.async.cg.shared.global [%0], [%1], 16;" :: "r"(d), "l"(s));
}

template<int KDIM, bool DO_TANH, bool ROUND_OUT>
__global__ void __launch_bounds__(256, 2) gemm_tc(const float* __restrict__ A,
                                                  const float* __restrict__ BT,
                                                  const float* __restrict__ bias,
                                                  float* __restrict__ C,
                                                  int N) {
    __shared__ __align__(16) float Asm[2 * SLOTF];   // 2 buffers A
    __shared__ __align__(16) float Bsm[2 * SLOTF];   // 2 buffers B
    const uint32_t sA = (uint32_t)__cvta_generic_to_shared(Asm);
    const uint32_t sB = (uint32_t)__cvta_generic_to_shared(Bsm);

    const int tid  = threadIdx.x;
    const int lane = tid & 31, warp = tid >> 5;
    const int wm = (warp >> 2) * 64;     // warp m-offset (0 or 64)
    const int wn = (warp & 3) * 32;      // warp n-offset
    const int g  = lane >> 2, tig = lane & 3;
    const int m0 = blockIdx.y * 128, n0 = blockIdx.x * 128;

    const float* Ag = A  + (size_t)m0 * KDIM;
    const float* Bg = BT + (size_t)n0 * KDIM;

    float acc[4][4][4];
#pragma unroll
    for (int i = 0; i < 4; ++i)
#pragma unroll
        for (int j = 0; j < 4; ++j)
#pragma unroll
            for (int r = 0; r < 4; ++r) acc[i][j][r] = 0.f;

    // per-thread cp.async: 512 float4 per operand slab, 2 per thread each
    auto load_slab = [&](int kt, int buf) {
#pragma unroll
        for (int i = 0; i < 2; ++i) {
            const int f = tid + i * 256;
            const int r = f >> 2, kq = f & 3;       // row 0..127, k-quad 0..3
            const uint32_t off = (uint32_t)(buf * SLOTB + (r * LDP + kq * 4) * 4);
            cp16(sA + off, Ag + (size_t)r * KDIM + kt + kq * 4);
            cp16(sB + off, Bg + (size_t)r * KDIM + kt + kq * 4);
        }
        asm volatile("cp.async.commit_group;");
    };

    load_slab(0, 0);
    const int nslab = KDIM / 16;
    for (int s = 0; s < nslab; ++s) {
        if (s + 1 < nslab) {
            load_slab((s + 1) * 16, (s + 1) & 1);
            asm volatile("cp.async.wait_group 1;");
        } else {
            asm volatile("cp.async.wait_group 0;");
        }
        __syncthreads();

        const float* Ab = Asm + (s & 1) * SLOTF;
        const float* Bb = Bsm + (s & 1) * SLOTF;
#pragma unroll
        for (int ks = 0; ks < 2; ++ks) {
            const int k0 = ks * 8;
            uint32_t a[4][4], bfr[4][2];
#pragma unroll
            for (int mt = 0; mt < 4; ++mt) {
                const int row = wm + mt * 16 + g;
                a[mt][0] = __float_as_uint(Ab[row * LDP + k0 + tig]);
                a[mt][1] = __float_as_uint(Ab[(row + 8) * LDP + k0 + tig]);
                a[mt][2] = __float_as_uint(Ab[row * LDP + k0 + tig + 4]);
                a[mt][3] = __float_as_uint(Ab[(row + 8) * LDP + k0 + tig + 4]);
            }
#pragma unroll
            for (int nt = 0; nt < 4; ++nt) {
                const int col = wn + nt * 8 + g;
                bfr[nt][0] = __float_as_uint(Bb[col * LDP + k0 + tig]);
                bfr[nt][1] = __float_as_uint(Bb[col * LDP + k0 + tig + 4]);
            }
#pragma unroll
            for (int mt = 0; mt < 4; ++mt)
#pragma unroll
                for (int nt = 0; nt < 4; ++nt)
                    asm volatile(
                        "mma.sync.aligned.m16n8k8.row.col.f32.tf32.tf32.f32 "
                        "{%0,%1,%2,%3}, {%4,%5,%6,%7}, {%8,%9}, {%0,%1,%2,%3};\n"
                        : "+f"(acc[mt][nt][0]), "+f"(acc[mt][nt][1]),
                          "+f"(acc[mt][nt][2]), "+f"(acc[mt][nt][3])
                        : "r"(a[mt][0]), "r"(a[mt][1]), "r"(a[mt][2]), "r"(a[mt][3]),
                          "r"(bfr[nt][0]), "r"(bfr[nt][1]));
        }
        __syncthreads();
    }

    // epilogue: bias + activation (+ tf32 rounding) via float2 stores
#pragma unroll
    for (int nt = 0; nt < 4; ++nt) {
        const int col = n0 + wn + nt * 8 + tig * 2;
        const float2 bv = *(const float2*)(bias + col);
#pragma unroll
        for (int mt = 0; mt < 4; ++mt) {
#pragma unroll
            for (int half = 0; half < 2; ++half) {
                const int row = m0 + wm + mt * 16 + g + half * 8;
                float v0 = acc[mt][nt][half * 2 + 0] + bv.x;
                float v1 = acc[mt][nt][half * 2 + 1] + bv.y;
                if (DO_TANH) { v0 = tanhf(v0); v1 = tanhf(v1); }
                if (ROUND_OUT) { v0 = to_tf32(v0); v1 = to_tf32(v1); }
                *(float2*)(C + (size_t)row * N + col) = make_float2(v0, v1);
            }
        }
    }
}

// =====================================================================
extern "C" void kernel_launch(void* const* d_in, const int* in_sizes, int n_in,
                              void* d_out, int out_size) {
    (void)in_sizes; (void)n_in; (void)out_size;
    const float* u      = (const float*)d_in[0];
    const float* D      = (const float*)d_in[1];
    const float* log_dt = (const float*)d_in[2];
    const float* C_re   = (const float*)d_in[3];
    const float* C_im   = (const float*)d_in[4];
    const float* W1     = (const float*)d_in[5];
    const float* b1     = (const float*)d_in[6];
    const float* W2     = (const float*)d_in[7];
    const float* b2     = (const float*)d_in[8];
    float* out = (float*)d_out;

    float *yg_p, *y2_p, *w1t_p, *w2t_p;
    cudaGetSymbolAddress((void**)&yg_p,  g_yg);
    cudaGetSymbolAddress((void**)&y2_p,  g_y2);
    cudaGetSymbolAddress((void**)&w1t_p, g_W1T);
    cudaGetSymbolAddress((void**)&w2t_p, g_W2T);

    prep_kernel<<<HH, 256>>>(log_dt, C_re, C_im);
    transpose_tf32<<<dim3(1024 / 32, 2048 / 32), 256>>>(W1, w1t_p, 2048, 1024);
    transpose_tf32<<<dim3(512 / 32, 1024 / 32), 256>>>(W2, w2t_p, 1024, 512);
    conv_kernel<<<BB * HH, 256>>>(u, D);
    // GEMM1: (8192 x 2048) @ W1 + b1 -> tanh -> g_y2 (tf32-rounded)
    gemm_tc<2048, true,  true ><<<dim3(8, 64), 256>>>(yg_p, w1t_p, b1, y2_p, 1024);
    // GEMM2: (8192 x 1024) @ W2 + b2 -> out
    gemm_tc<1024, false, false><<<dim3(4, 64), 256>>>(y2_p, w2t_p, b2, out, 512);
}